// round 4
// baseline (speedup 1.0000x reference)
#include <cuda_runtime.h>
#include <cstdint>
#include <cstddef>

#define NN 8192      // nodes == in_feats
#define DF 512       // feature dim
#define NE 262144    // edges

// ---------------- device scratch (no allocations allowed) ----------------
__device__ int   g_deg[NN];
__device__ int   g_off[NN + 1];
__device__ int   g_cur[NN];
__device__ int   g_col[NE];
__device__ float g_xT[(size_t)NN * DF];   // [node, feat] 16MB
__device__ float g_h [(size_t)DF * NN];   // [feat(d), node(k)] 16MB, K-major B operand

// ---------------- helpers ----------------
__device__ __forceinline__ uint32_t smem_u32(const void* p) {
    uint32_t a;
    asm("{ .reg .u64 t; cvta.to.shared.u64 t, %1; cvt.u32.u64 %0, t; }"
        : "=r"(a) : "l"(p));
    return a;
}
__device__ __forceinline__ uint32_t f2tf32(float f) {
    uint32_t u;
    asm("cvt.rna.tf32.f32 %0, %1;" : "=r"(u) : "f"(f));
    return u;
}
__device__ __forceinline__ void cp_async16(uint32_t saddr, const void* gaddr) {
    asm volatile("cp.async.cg.shared.global [%0], [%1], 16;"
                 :: "r"(saddr), "l"(gaddr) : "memory");
}
#define CP_COMMIT() asm volatile("cp.async.commit_group;" ::: "memory")
#define CP_WAIT1()  asm volatile("cp.async.wait_group 1;"  ::: "memory")

// mma.sync m16n8k8 tf32 (row.col), f32 accumulate
__device__ __forceinline__ void mma_tf32(float* c,
                                         uint32_t a0, uint32_t a1, uint32_t a2, uint32_t a3,
                                         uint32_t b0, uint32_t b1) {
    asm volatile(
        "mma.sync.aligned.m16n8k8.row.col.f32.tf32.tf32.f32 "
        "{%0,%1,%2,%3}, {%4,%5,%6,%7}, {%8,%9}, {%0,%1,%2,%3};"
        : "+f"(c[0]), "+f"(c[1]), "+f"(c[2]), "+f"(c[3])
        : "r"(a0), "r"(a1), "r"(a2), "r"(a3), "r"(b0), "r"(b1));
}

// ---------------- pre-GEMM kernels ----------------

__global__ void zero_deg_kernel() {
    int i = blockIdx.x * 256 + threadIdx.x;
    g_deg[i] = 0;
}

__global__ void count_deg_kernel(const int* __restrict__ adj) {
    int e = blockIdx.x * 256 + threadIdx.x;
    atomicAdd(&g_deg[adj[e]], 1);
}

// exclusive scan of 8192 degrees in a single 1024-thread block
__global__ void scan_kernel() {
    __shared__ int tot[1024];
    int t = threadIdx.x;
    int base = t * 8;
    int l[8];
    int s = 0;
#pragma unroll
    for (int j = 0; j < 8; ++j) { s += g_deg[base + j]; l[j] = s; }  // inclusive local
    tot[t] = s;
    __syncthreads();
    for (int off = 1; off < 1024; off <<= 1) {
        int v = (t >= off) ? tot[t - off] : 0;
        __syncthreads();
        tot[t] += v;
        __syncthreads();
    }
    int excl = (t == 0) ? 0 : tot[t - 1];
#pragma unroll
    for (int j = 0; j < 8; ++j) {
        int e = excl + ((j == 0) ? 0 : l[j - 1]);
        g_off[base + j] = e;
        g_cur[base + j] = e;
    }
    if (t == 1023) g_off[NN] = excl + l[7];
}

__global__ void scatter_kernel(const int* __restrict__ adj) {
    int e = blockIdx.x * 256 + threadIdx.x;
    int r = adj[e];
    int c = adj[NE + e];
    int pos = atomicAdd(&g_cur[r], 1);
    g_col[pos] = c;
}

// x [DF, NN] -> xT [NN, DF]
__global__ void transpose_kernel(const float* __restrict__ x) {
    __shared__ float tile[32][33];
    int n0 = blockIdx.x * 32;
    int d0 = blockIdx.y * 32;
    int tx = threadIdx.x, ty = threadIdx.y;
#pragma unroll
    for (int i = 0; i < 32; i += 8)
        tile[ty + i][tx] = x[(size_t)(d0 + ty + i) * NN + n0 + tx];
    __syncthreads();
#pragma unroll
    for (int i = 0; i < 32; i += 8)
        g_xT[(size_t)(n0 + ty + i) * DF + d0 + tx] = tile[tx][ty + i];
}

// one block per node: gather neighbor rows of xT, divide by deg, write h [DF, NN]
__global__ void agg_kernel() {
    int r = blockIdx.x;
    int t = threadIdx.x;  // 0..127 -> 512 feats as float4
    int beg = g_off[r];
    int end = g_off[r + 1];
    const float4* xt4 = reinterpret_cast<const float4*>(g_xT);
    float4 acc = make_float4(0.f, 0.f, 0.f, 0.f);
    for (int j = beg; j < end; ++j) {
        int c = g_col[j];
        float4 v = xt4[(size_t)c * 128 + t];
        acc.x += v.x; acc.y += v.y; acc.z += v.z; acc.w += v.w;
    }
    float inv = 1.0f / fmaxf((float)(end - beg), 1.0f);
    int d = t * 4;
    g_h[(size_t)(d + 0) * NN + r] = acc.x * inv;
    g_h[(size_t)(d + 1) * NN + r] = acc.y * inv;
    g_h[(size_t)(d + 2) * NN + r] = acc.z * inv;
    g_h[(size_t)(d + 3) * NN + r] = acc.w * inv;
}

// ---------------- tf32 mma.sync GEMM ----------------
// C[m, n] = sum_k W[m,k] * h[n,k];  out[n*NN + m] = relu(C[m,n])
// A = W [8192 x 8192] row-major (K-major). B = g_h [512 x 8192] (K-major).
// BM=128, BN=128, BK=32, 3-stage cp.async, 256 threads, warp tile 64x32.

#define BM 128
#define BN 128
#define BK 32
#define NK (NN / BK)          // 256 k-chunks
#define STAGE_BYTES 32768     // A 16KB + B 16KB
#define GEMM_SMEM (3 * STAGE_BYTES)

// swizzled smem byte offset within a 128-row x 128-byte tile
__device__ __forceinline__ uint32_t swz(int row, int colb) {
    return (uint32_t)(row * 128 + (colb ^ ((row & 7) << 4)));
}

__global__ __launch_bounds__(256, 1)
void gemm_kernel(const float* __restrict__ W, float* __restrict__ out) {
    extern __shared__ char smem[];
    uint32_t sb = smem_u32(smem);
    int tid  = threadIdx.x;
    int wid  = tid >> 5;
    int lane = tid & 31;
    int m0 = blockIdx.x * BM;
    int n0 = blockIdx.y * BN;

    int warp_m = (wid & 1) * 64;   // 2 warp-rows of 64
    int warp_n = (wid >> 1) * 32;  // 4 warp-cols of 32
    int lq = lane & 3, lh = lane >> 2;

    // per-thread fragment address components (byte offsets within a stage tile)
    uint32_t a_base[4], a_xor[4];
#pragma unroll
    for (int mt = 0; mt < 4; ++mt) {
        int r_lo = warp_m + mt * 16 + lh;           // hi row = +8, same (&7)
        a_base[mt] = (uint32_t)(r_lo * 128);
        a_xor[mt]  = (uint32_t)((r_lo & 7) << 4);
    }
    uint32_t b_base[4], b_xor[4];
#pragma unroll
    for (int nt = 0; nt < 4; ++nt) {
        int nr = warp_n + nt * 8 + lh;
        b_base[nt] = (uint32_t)(nr * 128);
        b_xor[nt]  = (uint32_t)((nr & 7) << 4);
    }

    // global load coords for cp.async
    int gc = tid & 7;      // 16B chunk within 128B row
    int gr = tid >> 3;     // base row 0..31, +32*i

    float acc[4][4][4];
#pragma unroll
    for (int mt = 0; mt < 4; ++mt)
#pragma unroll
        for (int nt = 0; nt < 4; ++nt)
#pragma unroll
            for (int i = 0; i < 4; ++i) acc[mt][nt][i] = 0.f;

    const float* Hp = g_h;

    // ---- prologue: load stages 0, 1 ----
#pragma unroll
    for (int s = 0; s < 2; ++s) {
        uint32_t abuf = sb + s * STAGE_BYTES;
        uint32_t bbuf = abuf + 16384;
#pragma unroll
        for (int i = 0; i < 4; ++i) {
            int row = gr + i * 32;
            uint32_t so = swz(row, gc * 16);
            cp_async16(abuf + so, W  + (size_t)(m0 + row) * NN + s * BK + gc * 4);
            cp_async16(bbuf + so, Hp + (size_t)(n0 + row) * NN + s * BK + gc * 4);
        }
        CP_COMMIT();
    }

    for (int kt = 0; kt < NK; ++kt) {
        CP_WAIT1();
        __syncthreads();

        int kn = kt + 2;
        if (kn < NK) {
            int s = kn % 3;
            uint32_t abuf = sb + s * STAGE_BYTES;
            uint32_t bbuf = abuf + 16384;
#pragma unroll
            for (int i = 0; i < 4; ++i) {
                int row = gr + i * 32;
                uint32_t so = swz(row, gc * 16);
                cp_async16(abuf + so, W  + (size_t)(m0 + row) * NN + kn * BK + gc * 4);
                cp_async16(bbuf + so, Hp + (size_t)(n0 + row) * NN + kn * BK + gc * 4);
            }
            CP_COMMIT();
        }

        int cs = kt % 3;
        uint32_t abuf = sb + cs * STAGE_BYTES;
        uint32_t bbuf = abuf + 16384;

#pragma unroll
        for (int k8 = 0; k8 < 4; ++k8) {
            int colb = k8 * 32 + lq * 4;   // byte col of a0/b0
            uint32_t af[4][4];
#pragma unroll
            for (int mt = 0; mt < 4; ++mt) {
                uint32_t lo0 = abuf + a_base[mt] + ((uint32_t)colb        ^ a_xor[mt]);
                uint32_t lo2 = abuf + a_base[mt] + ((uint32_t)(colb + 16) ^ a_xor[mt]);
                float v0, v1, v2, v3;
                asm volatile("ld.shared.f32 %0, [%1];" : "=f"(v0) : "r"(lo0));
                asm volatile("ld.shared.f32 %0, [%1];" : "=f"(v1) : "r"(lo0 + 8 * 128));
                asm volatile("ld.shared.f32 %0, [%1];" : "=f"(v2) : "r"(lo2));
                asm volatile("ld.shared.f32 %0, [%1];" : "=f"(v3) : "r"(lo2 + 8 * 128));
                af[mt][0] = f2tf32(v0); af[mt][1] = f2tf32(v1);
                af[mt][2] = f2tf32(v2); af[mt][3] = f2tf32(v3);
            }
            uint32_t bf[4][2];
#pragma unroll
            for (int nt = 0; nt < 4; ++nt) {
                uint32_t k0 = bbuf + b_base[nt] + ((uint32_t)colb        ^ b_xor[nt]);
                uint32_t k1 = bbuf + b_base[nt] + ((uint32_t)(colb + 16) ^ b_xor[nt]);
                float v0, v1;
                asm volatile("ld.shared.f32 %0, [%1];" : "=f"(v0) : "r"(k0));
                asm volatile("ld.shared.f32 %0, [%1];" : "=f"(v1) : "r"(k1));
                bf[nt][0] = f2tf32(v0); bf[nt][1] = f2tf32(v1);
            }
#pragma unroll
            for (int mt = 0; mt < 4; ++mt)
#pragma unroll
                for (int nt = 0; nt < 4; ++nt)
                    mma_tf32(acc[mt][nt],
                             af[mt][0], af[mt][1], af[mt][2], af[mt][3],
                             bf[nt][0], bf[nt][1]);
        }
    }

    // ---- epilogue: relu + transposed store out[n*NN + m] ----
#pragma unroll
    for (int mt = 0; mt < 4; ++mt) {
        int m_lo = m0 + warp_m + mt * 16 + lh;
        int m_hi = m_lo + 8;
#pragma unroll
        for (int nt = 0; nt < 4; ++nt) {
            int nb = n0 + warp_n + nt * 8 + 2 * lq;
            float* o0 = out + (size_t)nb * NN;
            float* o1 = o0 + NN;
            o0[m_lo] = fmaxf(acc[mt][nt][0], 0.f);
            o1[m_lo] = fmaxf(acc[mt][nt][1], 0.f);
            o0[m_hi] = fmaxf(acc[mt][nt][2], 0.f);
            o1[m_hi] = fmaxf(acc[mt][nt][3], 0.f);
        }
    }
}

// ---------------- launcher ----------------
extern "C" void kernel_launch(void* const* d_in, const int* in_sizes, int n_in,
                              void* d_out, int out_size) {
    (void)in_sizes; (void)n_in; (void)out_size;
    const float* x   = (const float*)d_in[0];   // [512, 8192] f32
    const int*   adj = (const int*)d_in[1];     // [2, 262144] i32
    const float* W   = (const float*)d_in[2];   // [8192, 8192] f32
    float* out = (float*)d_out;                 // [512, 8192] f32

    zero_deg_kernel<<<NN / 256, 256>>>();
    count_deg_kernel<<<NE / 256, 256>>>(adj);
    scan_kernel<<<1, 1024>>>();
    scatter_kernel<<<NE / 256, 256>>>(adj);
    transpose_kernel<<<dim3(NN / 32, DF / 32), dim3(32, 8)>>>(x);
    agg_kernel<<<NN, 128>>>();

    cudaFuncSetAttribute(gemm_kernel, cudaFuncAttributeMaxDynamicSharedMemorySize, GEMM_SMEM);
    gemm_kernel<<<dim3(NN / BM, DF / BN), 256, GEMM_SMEM>>>(W, out);
}

// round 5
// speedup vs baseline: 1.5019x; 1.5019x over previous
#include <cuda_runtime.h>
#include <cuda_fp16.h>
#include <cstdint>
#include <cstddef>

#define NN 8192      // nodes == in_feats
#define DF 512       // feature dim
#define NE 262144    // edges

// ---------------- device scratch (no allocations allowed) ----------------
__device__ int    g_deg[NN];
__device__ int    g_off[NN + 1];
__device__ int    g_cur[NN];
__device__ int    g_col[NE];
__device__ float  g_xT[(size_t)NN * DF];      // [node, feat] 16MB
__device__ __half g_hh[(size_t)DF * NN];      // [feat(n), node(k)] fp16 B operand, 8MB
__device__ __half g_Wh[(size_t)NN * NN];      // fp16 copy of W, 128MB

// ---------------- helpers ----------------
__device__ __forceinline__ uint32_t smem_u32(const void* p) {
    uint32_t a;
    asm("{ .reg .u64 t; cvta.to.shared.u64 t, %1; cvt.u32.u64 %0, t; }"
        : "=r"(a) : "l"(p));
    return a;
}
__device__ __forceinline__ void cp_async16(uint32_t saddr, const void* gaddr) {
    asm volatile("cp.async.cg.shared.global [%0], [%1], 16;"
                 :: "r"(saddr), "l"(gaddr) : "memory");
}
#define CP_COMMIT() asm volatile("cp.async.commit_group;" ::: "memory")
#define CP_WAIT1()  asm volatile("cp.async.wait_group 1;"  ::: "memory")

#define LDSM4(r0, r1, r2, r3, addr) \
    asm volatile("ldmatrix.sync.aligned.m8n8.x4.shared.b16 {%0,%1,%2,%3}, [%4];" \
                 : "=r"(r0), "=r"(r1), "=r"(r2), "=r"(r3) : "r"(addr))

__device__ __forceinline__ void mma_f16(float* c,
                                        uint32_t a0, uint32_t a1, uint32_t a2, uint32_t a3,
                                        uint32_t b0, uint32_t b1) {
    asm volatile(
        "mma.sync.aligned.m16n8k16.row.col.f32.f16.f16.f32 "
        "{%0,%1,%2,%3}, {%4,%5,%6,%7}, {%8,%9}, {%0,%1,%2,%3};"
        : "+f"(c[0]), "+f"(c[1]), "+f"(c[2]), "+f"(c[3])
        : "r"(a0), "r"(a1), "r"(a2), "r"(a3), "r"(b0), "r"(b1));
}

// ---------------- pre-GEMM kernels ----------------

__global__ void zero_deg_kernel() {
    int i = blockIdx.x * 256 + threadIdx.x;
    g_deg[i] = 0;
}

__global__ void count_deg_kernel(const int* __restrict__ adj) {
    int e = blockIdx.x * 256 + threadIdx.x;
    atomicAdd(&g_deg[adj[e]], 1);
}

// exclusive scan of 8192 degrees in a single 1024-thread block
__global__ void scan_kernel() {
    __shared__ int tot[1024];
    int t = threadIdx.x;
    int base = t * 8;
    int l[8];
    int s = 0;
#pragma unroll
    for (int j = 0; j < 8; ++j) { s += g_deg[base + j]; l[j] = s; }  // inclusive local
    tot[t] = s;
    __syncthreads();
    for (int off = 1; off < 1024; off <<= 1) {
        int v = (t >= off) ? tot[t - off] : 0;
        __syncthreads();
        tot[t] += v;
        __syncthreads();
    }
    int excl = (t == 0) ? 0 : tot[t - 1];
#pragma unroll
    for (int j = 0; j < 8; ++j) {
        int e = excl + ((j == 0) ? 0 : l[j - 1]);
        g_off[base + j] = e;
        g_cur[base + j] = e;
    }
    if (t == 1023) g_off[NN] = excl + l[7];
}

__global__ void scatter_kernel(const int* __restrict__ adj) {
    int e = blockIdx.x * 256 + threadIdx.x;
    int r = adj[e];
    int c = adj[NE + e];
    int pos = atomicAdd(&g_cur[r], 1);
    g_col[pos] = c;
}

// x [DF, NN] -> xT [NN, DF]
__global__ void transpose_kernel(const float* __restrict__ x) {
    __shared__ float tile[32][33];
    int n0 = blockIdx.x * 32;
    int d0 = blockIdx.y * 32;
    int tx = threadIdx.x, ty = threadIdx.y;
#pragma unroll
    for (int i = 0; i < 32; i += 8)
        tile[ty + i][tx] = x[(size_t)(d0 + ty + i) * NN + n0 + tx];
    __syncthreads();
#pragma unroll
    for (int i = 0; i < 32; i += 8)
        g_xT[(size_t)(n0 + ty + i) * DF + d0 + tx] = tile[tx][ty + i];
}

// convert W (f32, 64M elems) -> fp16 copy
__global__ void wconv_kernel(const float* __restrict__ W) {
    size_t i = ((size_t)blockIdx.x * 256 + threadIdx.x) * 4;
    float4 v = *reinterpret_cast<const float4*>(W + i);
    __half2* o = reinterpret_cast<__half2*>(g_Wh + i);
    o[0] = __floats2half2_rn(v.x, v.y);
    o[1] = __floats2half2_rn(v.z, v.w);
}

// one block per node: gather neighbor rows of xT, divide by deg, write h fp16 [DF, NN]
__global__ void agg_kernel() {
    int r = blockIdx.x;
    int t = threadIdx.x;  // 0..127 -> 512 feats as float4
    int beg = g_off[r];
    int end = g_off[r + 1];
    const float4* xt4 = reinterpret_cast<const float4*>(g_xT);
    float4 acc = make_float4(0.f, 0.f, 0.f, 0.f);
    for (int j = beg; j < end; ++j) {
        int c = g_col[j];
        float4 v = xt4[(size_t)c * 128 + t];
        acc.x += v.x; acc.y += v.y; acc.z += v.z; acc.w += v.w;
    }
    float inv = 1.0f / fmaxf((float)(end - beg), 1.0f);
    int d = t * 4;
    g_hh[(size_t)(d + 0) * NN + r] = __float2half_rn(acc.x * inv);
    g_hh[(size_t)(d + 1) * NN + r] = __float2half_rn(acc.y * inv);
    g_hh[(size_t)(d + 2) * NN + r] = __float2half_rn(acc.z * inv);
    g_hh[(size_t)(d + 3) * NN + r] = __float2half_rn(acc.w * inv);
}

// ---------------- fp16 mma.sync GEMM ----------------
// C[m, n] = sum_k Wh[m,k] * hh[n,k];  out[n*NN + m] = relu(C[m,n])
// A = g_Wh [8192 x 8192] K-major. B = g_hh [512 x 8192] K-major.
// BM=128, BN=128, BK=64 (fp16: 128B rows), 3-stage cp.async, 256 threads,
// warp tile 64x32, m16n8k16 with ldmatrix.x4 fragment loads.

#define BM 128
#define BN 128
#define BK 64
#define NK (NN / BK)          // 128 k-chunks
#define TILE_BYTES 16384      // 128 rows x 128 bytes
#define STAGE_BYTES 32768     // A + B
#define GEMM_SMEM (3 * STAGE_BYTES)

__device__ __forceinline__ uint32_t swz(int row, int colb) {
    return (uint32_t)(row * 128 + (colb ^ ((row & 7) << 4)));
}

__global__ __launch_bounds__(256, 1)
void gemm_kernel(float* __restrict__ out) {
    extern __shared__ char smem[];
    uint32_t sb = smem_u32(smem);
    int tid  = threadIdx.x;
    int wid  = tid >> 5;
    int lane = tid & 31;
    int m0 = blockIdx.x * BM;
    int n0 = blockIdx.y * BN;

    int warp_m = (wid & 1) * 64;   // 2 warp-rows of 64
    int warp_n = (wid >> 1) * 32;  // 4 warp-cols of 32
    int lq = lane & 3, lh = lane >> 2;

    // ---- per-lane ldmatrix address components ----
    // A: matrices (m0-7,k0-7),(m8-15,k0-7),(m0-7,k8-15),(m8-15,k8-15)
    //    lane row = (lane&7) + 8*((lane>>3)&1); k-16B-half = lane>>4
    int a_r_lane = (lane & 7) + 8 * ((lane >> 3) & 1);
    uint32_t a_kx = (uint32_t)(16 * (lane >> 4));
    uint32_t a_row128[4], a_xr[4];
#pragma unroll
    for (int mt = 0; mt < 4; ++mt) {
        int r = warp_m + mt * 16 + a_r_lane;
        a_row128[mt] = (uint32_t)(r * 128);
        a_xr[mt] = (uint32_t)((r & 7) << 4);
    }
    // B: for n-tile pair p (tiles 2p, 2p+1): matrices (nt,k0-7),(nt,k8-15),(nt+1,k0-7),(nt+1,k8-15)
    //    lane n-row = warp_n + (2p + (lane>>4))*8 + (lane&7); k-16B-half = (lane>>3)&1
    uint32_t b_kx = (uint32_t)(16 * ((lane >> 3) & 1));
    uint32_t b_row128[2], b_xr[2];
#pragma unroll
    for (int p = 0; p < 2; ++p) {
        int n = warp_n + (2 * p + (lane >> 4)) * 8 + (lane & 7);
        b_row128[p] = (uint32_t)(n * 128);
        b_xr[p] = (uint32_t)((n & 7) << 4);
    }

    // global->smem coords for cp.async (8 x 16B chunks per 128B row)
    int gc = tid & 7;      // 16B chunk within row
    int gr = tid >> 3;     // base row 0..31, +32*i

    float acc[4][4][4];
#pragma unroll
    for (int mt = 0; mt < 4; ++mt)
#pragma unroll
        for (int nt = 0; nt < 4; ++nt)
#pragma unroll
            for (int i = 0; i < 4; ++i) acc[mt][nt][i] = 0.f;

    const __half* A = g_Wh;
    const __half* B = g_hh;

    // ---- prologue: stages 0, 1 ----
#pragma unroll
    for (int s = 0; s < 2; ++s) {
        uint32_t abuf = sb + s * STAGE_BYTES;
        uint32_t bbuf = abuf + TILE_BYTES;
#pragma unroll
        for (int i = 0; i < 4; ++i) {
            int row = gr + i * 32;
            uint32_t so = swz(row, gc * 16);
            cp_async16(abuf + so, A + (size_t)(m0 + row) * NN + s * BK + gc * 8);
            cp_async16(bbuf + so, B + (size_t)(n0 + row) * NN + s * BK + gc * 8);
        }
        CP_COMMIT();
    }

    for (int kt = 0; kt < NK; ++kt) {
        CP_WAIT1();
        __syncthreads();

        int kn = kt + 2;
        if (kn < NK) {
            int s = kn % 3;
            uint32_t abuf = sb + s * STAGE_BYTES;
            uint32_t bbuf = abuf + TILE_BYTES;
#pragma unroll
            for (int i = 0; i < 4; ++i) {
                int row = gr + i * 32;
                uint32_t so = swz(row, gc * 16);
                cp_async16(abuf + so, A + (size_t)(m0 + row) * NN + kn * BK + gc * 8);
                cp_async16(bbuf + so, B + (size_t)(n0 + row) * NN + kn * BK + gc * 8);
            }
            CP_COMMIT();
        }

        int cs = kt % 3;
        uint32_t abuf = sb + cs * STAGE_BYTES;
        uint32_t bbuf = abuf + TILE_BYTES;

#pragma unroll
        for (int c = 0; c < 4; ++c) {      // 4 k16 steps in BK=64
            uint32_t cb = (uint32_t)(c * 32);
            uint32_t af[4][4];
#pragma unroll
            for (int mt = 0; mt < 4; ++mt) {
                uint32_t ptr = abuf + a_row128[mt] + ((cb + a_kx) ^ a_xr[mt]);
                LDSM4(af[mt][0], af[mt][1], af[mt][2], af[mt][3], ptr);
            }
            uint32_t bf[4][2];
#pragma unroll
            for (int p = 0; p < 2; ++p) {
                uint32_t ptr = bbuf + b_row128[p] + ((cb + b_kx) ^ b_xr[p]);
                uint32_t r0, r1, r2, r3;
                LDSM4(r0, r1, r2, r3, ptr);
                bf[2 * p][0] = r0;     bf[2 * p][1] = r1;
                bf[2 * p + 1][0] = r2; bf[2 * p + 1][1] = r3;
            }
#pragma unroll
            for (int mt = 0; mt < 4; ++mt)
#pragma unroll
                for (int nt = 0; nt < 4; ++nt)
                    mma_f16(acc[mt][nt],
                            af[mt][0], af[mt][1], af[mt][2], af[mt][3],
                            bf[nt][0], bf[nt][1]);
        }
    }

    // ---- epilogue: relu + transposed store out[n*NN + m] ----
#pragma unroll
    for (int mt = 0; mt < 4; ++mt) {
        int m_lo = m0 + warp_m + mt * 16 + lh;
        int m_hi = m_lo + 8;
#pragma unroll
        for (int nt = 0; nt < 4; ++nt) {
            int nb = n0 + warp_n + nt * 8 + 2 * lq;
            float* o0 = out + (size_t)nb * NN;
            float* o1 = o0 + NN;
            o0[m_lo] = fmaxf(acc[mt][nt][0], 0.f);
            o1[m_lo] = fmaxf(acc[mt][nt][1], 0.f);
            o0[m_hi] = fmaxf(acc[mt][nt][2], 0.f);
            o1[m_hi] = fmaxf(acc[mt][nt][3], 0.f);
        }
    }
}

// ---------------- launcher ----------------
extern "C" void kernel_launch(void* const* d_in, const int* in_sizes, int n_in,
                              void* d_out, int out_size) {
    (void)in_sizes; (void)n_in; (void)out_size;
    const float* x   = (const float*)d_in[0];   // [512, 8192] f32
    const int*   adj = (const int*)d_in[1];     // [2, 262144] i32
    const float* W   = (const float*)d_in[2];   // [8192, 8192] f32
    float* out = (float*)d_out;                 // [512, 8192] f32

    wconv_kernel<<<(int)(((size_t)NN * NN) / (256 * 4)), 256>>>(W);
    zero_deg_kernel<<<NN / 256, 256>>>();
    count_deg_kernel<<<NE / 256, 256>>>(adj);
    scan_kernel<<<1, 1024>>>();
    scatter_kernel<<<NE / 256, 256>>>(adj);
    transpose_kernel<<<dim3(NN / 32, DF / 32), dim3(32, 8)>>>(x);
    agg_kernel<<<NN, 128>>>();

    cudaFuncSetAttribute(gemm_kernel, cudaFuncAttributeMaxDynamicSharedMemorySize, GEMM_SMEM);
    gemm_kernel<<<dim3(NN / BM, DF / BN), 256, GEMM_SMEM>>>(out);
}

// round 6
// speedup vs baseline: 1.6630x; 1.1073x over previous
#include <cuda_runtime.h>
#include <cuda_fp16.h>
#include <cstdint>
#include <cstddef>

#define NN 8192      // nodes == in_feats
#define DF 512       // feature dim
#define NE 262144    // edges

// ---------------- device scratch (no allocations allowed) ----------------
__device__ int    g_deg[NN];
__device__ int    g_off[NN + 1];
__device__ int    g_cur[NN];
__device__ int    g_col[NE];
__device__ __half g_xh[(size_t)NN * DF];      // [node, feat] fp16, 8MB
__device__ __half g_hh[(size_t)DF * NN];      // [feat(n), node(k)] fp16 B operand, 8MB

// ---------------- helpers ----------------
__device__ __forceinline__ uint32_t smem_u32(const void* p) {
    uint32_t a;
    asm("{ .reg .u64 t; cvta.to.shared.u64 t, %1; cvt.u32.u64 %0, t; }"
        : "=r"(a) : "l"(p));
    return a;
}
__device__ __forceinline__ void cp_async16(uint32_t saddr, const void* gaddr) {
    asm volatile("cp.async.cg.shared.global [%0], [%1], 16;"
                 :: "r"(saddr), "l"(gaddr) : "memory");
}
#define CP_COMMIT() asm volatile("cp.async.commit_group;" ::: "memory")
#define CP_WAIT1()  asm volatile("cp.async.wait_group 1;"  ::: "memory")
#define CP_WAIT0()  asm volatile("cp.async.wait_group 0;"  ::: "memory")

#define LDSM4(r0, r1, r2, r3, addr) \
    asm volatile("ldmatrix.sync.aligned.m8n8.x4.shared.b16 {%0,%1,%2,%3}, [%4];" \
                 : "=r"(r0), "=r"(r1), "=r"(r2), "=r"(r3) : "r"(addr))

__device__ __forceinline__ void mma_f16(float* c,
                                        uint32_t a0, uint32_t a1, uint32_t a2, uint32_t a3,
                                        uint32_t b0, uint32_t b1) {
    asm volatile(
        "mma.sync.aligned.m16n8k16.row.col.f32.f16.f16.f32 "
        "{%0,%1,%2,%3}, {%4,%5,%6,%7}, {%8,%9}, {%0,%1,%2,%3};"
        : "+f"(c[0]), "+f"(c[1]), "+f"(c[2]), "+f"(c[3])
        : "r"(a0), "r"(a1), "r"(a2), "r"(a3), "r"(b0), "r"(b1));
}

// ---------------- pre-GEMM kernels ----------------

__global__ void zero_deg_kernel() {
    int i = blockIdx.x * 256 + threadIdx.x;
    g_deg[i] = 0;
}

__global__ void count_deg_kernel(const int* __restrict__ adj) {
    int e = blockIdx.x * 256 + threadIdx.x;
    atomicAdd(&g_deg[adj[e]], 1);
}

// exclusive scan of 8192 degrees: 1024 threads, shfl hierarchical, 2 syncs
__global__ void scan_kernel() {
    __shared__ int wsum[32];
    int t = threadIdx.x, lane = t & 31, wid = t >> 5;
    int base = t * 8;
    int l[8];
    int s = 0;
#pragma unroll
    for (int j = 0; j < 8; ++j) { s += g_deg[base + j]; l[j] = s; }  // local inclusive
    int tot = s;
    // inclusive warp scan of per-thread totals
#pragma unroll
    for (int o = 1; o < 32; o <<= 1) {
        int v = __shfl_up_sync(0xffffffffu, s, o);
        if (lane >= o) s += v;
    }
    if (lane == 31) wsum[wid] = s;
    __syncthreads();
    if (wid == 0) {
        int w = wsum[lane];
#pragma unroll
        for (int o = 1; o < 32; o <<= 1) {
            int v = __shfl_up_sync(0xffffffffu, w, o);
            if (lane >= o) w += v;
        }
        wsum[lane] = w;
    }
    __syncthreads();
    int warp_base = wid ? wsum[wid - 1] : 0;
    int excl = warp_base + s - tot;   // exclusive prefix for this thread's block of 8
#pragma unroll
    for (int j = 0; j < 8; ++j) {
        int e = excl + ((j == 0) ? 0 : l[j - 1]);
        g_off[base + j] = e;
        g_cur[base + j] = e;
    }
    if (t == 1023) g_off[NN] = warp_base + s;  // = NE
}

__global__ void scatter_kernel(const int* __restrict__ adj) {
    int e = blockIdx.x * 256 + threadIdx.x;
    int r = adj[e];
    int c = adj[NE + e];
    int pos = atomicAdd(&g_cur[r], 1);
    g_col[pos] = c;
}

// x [DF, NN] f32 -> g_xh [NN, DF] fp16
__global__ void transpose_kernel(const float* __restrict__ x) {
    __shared__ float tile[32][33];
    int n0 = blockIdx.x * 32;
    int d0 = blockIdx.y * 32;
    int tx = threadIdx.x, ty = threadIdx.y;
#pragma unroll
    for (int i = 0; i < 32; i += 8)
        tile[ty + i][tx] = x[(size_t)(d0 + ty + i) * NN + n0 + tx];
    __syncthreads();
#pragma unroll
    for (int i = 0; i < 32; i += 8)
        g_xh[(size_t)(n0 + ty + i) * DF + d0 + tx] = __float2half_rn(tile[tx][ty + i]);
}

// one block per node: gather fp16 neighbor rows, f32 accumulate, write h fp16 [DF, NN]
__global__ void agg_kernel() {
    int r = blockIdx.x;
    int t = threadIdx.x;  // 0..127 -> 512 feats as 4 halves each
    int beg = g_off[r];
    int end = g_off[r + 1];
    const uint2* xh = reinterpret_cast<const uint2*>(g_xh);  // 128 uint2 per node row
    float ax = 0.f, ay = 0.f, az = 0.f, aw = 0.f;
    for (int j = beg; j < end; ++j) {
        int c = g_col[j];
        uint2 v = xh[(size_t)c * 128 + t];
        __half2 h0 = *reinterpret_cast<__half2*>(&v.x);
        __half2 h1 = *reinterpret_cast<__half2*>(&v.y);
        float2 f0 = __half22float2(h0);
        float2 f1 = __half22float2(h1);
        ax += f0.x; ay += f0.y; az += f1.x; aw += f1.y;
    }
    float inv = 1.0f / fmaxf((float)(end - beg), 1.0f);
    int d = t * 4;
    g_hh[(size_t)(d + 0) * NN + r] = __float2half_rn(ax * inv);
    g_hh[(size_t)(d + 1) * NN + r] = __float2half_rn(ay * inv);
    g_hh[(size_t)(d + 2) * NN + r] = __float2half_rn(az * inv);
    g_hh[(size_t)(d + 3) * NN + r] = __float2half_rn(aw * inv);
}

// ---------------- fp16 mma.sync GEMM with in-kernel W conversion ----------------
// C[m, n] = sum_k W[m,k] * hh[n,k];  out[n*NN + m] = relu(C[m,n])
// A = W f32 (LDG -> cvt -> STS fp16, 2-stage smem, 1-chunk reg lookahead).
// B = g_hh fp16 K-major (cp.async, 3-stage smem).
// BM=128, BN=128, BK=64, 256 threads, warp tile 64x32, m16n8k16 + ldmatrix.x4.

#define BM 128
#define BN 128
#define BK 64
#define NK (NN / BK)          // 128 k-chunks
#define TILE_BYTES 16384      // 128 rows x 128 bytes (fp16)
#define A_REGION 0            // A stages: 0, 16384
#define B_REGION 32768        // B stages: 32768, 49152, 65536
#define GEMM_SMEM 81920

__device__ __forceinline__ uint32_t swz(int row, int colb) {
    return (uint32_t)(row * 128 + (colb ^ ((row & 7) << 4)));
}

__global__ __launch_bounds__(256, 1)
void gemm_kernel(const float* __restrict__ W, float* __restrict__ out) {
    extern __shared__ char smem[];
    uint32_t sb = smem_u32(smem);
    int tid  = threadIdx.x;
    int wid  = tid >> 5;
    int lane = tid & 31;
    int m0 = blockIdx.y * BM;   // grid.y = m (64)
    int n0 = blockIdx.x * BN;   // grid.x = n (4) -> same-m CTAs adjacent, share W via L2

    int warp_m = (wid & 1) * 64;
    int warp_n = (wid >> 1) * 32;
    int lq = lane & 3, lh = lane >> 2;

    // ldmatrix address components (identical fragment layout to R5)
    int a_r_lane = (lane & 7) + 8 * ((lane >> 3) & 1);
    uint32_t a_kx = (uint32_t)(16 * (lane >> 4));
    uint32_t a_row128[4], a_xr[4];
#pragma unroll
    for (int mt = 0; mt < 4; ++mt) {
        int r = warp_m + mt * 16 + a_r_lane;
        a_row128[mt] = (uint32_t)(r * 128);
        a_xr[mt] = (uint32_t)((r & 7) << 4);
    }
    uint32_t b_kx = (uint32_t)(16 * ((lane >> 3) & 1));
    uint32_t b_row128[2], b_xr[2];
#pragma unroll
    for (int p = 0; p < 2; ++p) {
        int n = warp_n + (2 * p + (lane >> 4)) * 8 + (lane & 7);
        b_row128[p] = (uint32_t)(n * 128);
        b_xr[p] = (uint32_t)((n & 7) << 4);
    }

    // A f32 global-load coords: 2048 float4 per chunk; idx = tid + i*256
    int a_r0 = tid >> 4;          // +16*i
    int a_c4 = tid & 15;          // float4 col within row (0..15)
    // B cp.async coords: 1024 16B chunks; idx = tid + i*256
    int b_gc = tid & 7;
    int b_gr = tid >> 3;          // +32*i

    float acc[4][4][4];
#pragma unroll
    for (int mt = 0; mt < 4; ++mt)
#pragma unroll
        for (int nt = 0; nt < 4; ++nt)
#pragma unroll
            for (int i = 0; i < 4; ++i) acc[mt][nt][i] = 0.f;

    const __half* B = g_hh;
    float4 areg[8];

    // ---- A chunk loaders ----
    auto ldA = [&](int kt) {
#pragma unroll
        for (int i = 0; i < 8; ++i) {
            int row = a_r0 + i * 16;
            areg[i] = *reinterpret_cast<const float4*>(
                W + (size_t)(m0 + row) * NN + kt * BK + a_c4 * 4);
        }
    };
    auto stsA = [&](int stage) {
        char* ab = smem + A_REGION + stage * TILE_BYTES;
        int colb = a_c4 * 8;
#pragma unroll
        for (int i = 0; i < 8; ++i) {
            int row = a_r0 + i * 16;
            uint32_t off = (uint32_t)(row * 128 + (colb ^ ((row & 7) << 4)));
            __half2 h0 = __floats2half2_rn(areg[i].x, areg[i].y);
            __half2 h1 = __floats2half2_rn(areg[i].z, areg[i].w);
            uint2 v;
            v.x = *reinterpret_cast<uint32_t*>(&h0);
            v.y = *reinterpret_cast<uint32_t*>(&h1);
            *reinterpret_cast<uint2*>(ab + off) = v;
        }
    };
    auto cpB = [&](int kt, int stage) {
        uint32_t bbuf = sb + B_REGION + stage * TILE_BYTES;
#pragma unroll
        for (int i = 0; i < 4; ++i) {
            int row = b_gr + i * 32;
            uint32_t so = swz(row, b_gc * 16);
            cp_async16(bbuf + so, B + (size_t)(n0 + row) * NN + kt * BK + b_gc * 8);
        }
        CP_COMMIT();
    };

    // ---- prologue ----
    ldA(0);
    cpB(0, 0);
    cpB(1, 1);
    stsA(0);
    ldA(1);

    for (int kt = 0; kt < NK; ++kt) {
        if (kt == NK - 1) { CP_WAIT0(); } else { CP_WAIT1(); }
        __syncthreads();

        if (kt + 1 < NK) stsA((kt + 1) & 1);
        if (kt + 2 < NK) {
            ldA(kt + 2);
            cpB(kt + 2, (kt + 2) % 3);
        }

        uint32_t abuf = sb + A_REGION + (kt & 1) * TILE_BYTES;
        uint32_t bbuf = sb + B_REGION + (kt % 3) * TILE_BYTES;

#pragma unroll
        for (int c = 0; c < 4; ++c) {      // 4 k16 steps in BK=64
            uint32_t cb = (uint32_t)(c * 32);
            uint32_t af[4][4];
#pragma unroll
            for (int mt = 0; mt < 4; ++mt) {
                uint32_t ptr = abuf + a_row128[mt] + ((cb + a_kx) ^ a_xr[mt]);
                LDSM4(af[mt][0], af[mt][1], af[mt][2], af[mt][3], ptr);
            }
            uint32_t bf[4][2];
#pragma unroll
            for (int p = 0; p < 2; ++p) {
                uint32_t ptr = bbuf + b_row128[p] + ((cb + b_kx) ^ b_xr[p]);
                uint32_t r0, r1, r2, r3;
                LDSM4(r0, r1, r2, r3, ptr);
                bf[2 * p][0] = r0;     bf[2 * p][1] = r1;
                bf[2 * p + 1][0] = r2; bf[2 * p + 1][1] = r3;
            }
#pragma unroll
            for (int mt = 0; mt < 4; ++mt)
#pragma unroll
                for (int nt = 0; nt < 4; ++nt)
                    mma_f16(acc[mt][nt],
                            af[mt][0], af[mt][1], af[mt][2], af[mt][3],
                            bf[nt][0], bf[nt][1]);
        }
    }

    // ---- epilogue: relu + transposed store out[n*NN + m] ----
#pragma unroll
    for (int mt = 0; mt < 4; ++mt) {
        int m_lo = m0 + warp_m + mt * 16 + lh;
        int m_hi = m_lo + 8;
#pragma unroll
        for (int nt = 0; nt < 4; ++nt) {
            int nb = n0 + warp_n + nt * 8 + 2 * lq;
            float* o0 = out + (size_t)nb * NN;
            float* o1 = o0 + NN;
            o0[m_lo] = fmaxf(acc[mt][nt][0], 0.f);
            o1[m_lo] = fmaxf(acc[mt][nt][1], 0.f);
            o0[m_hi] = fmaxf(acc[mt][nt][2], 0.f);
            o1[m_hi] = fmaxf(acc[mt][nt][3], 0.f);
        }
    }
}

// ---------------- launcher ----------------
extern "C" void kernel_launch(void* const* d_in, const int* in_sizes, int n_in,
                              void* d_out, int out_size) {
    (void)in_sizes; (void)n_in; (void)out_size;
    const float* x   = (const float*)d_in[0];   // [512, 8192] f32
    const int*   adj = (const int*)d_in[1];     // [2, 262144] i32
    const float* W   = (const float*)d_in[2];   // [8192, 8192] f32
    float* out = (float*)d_out;                 // [512, 8192] f32

    zero_deg_kernel<<<NN / 256, 256>>>();
    count_deg_kernel<<<NE / 256, 256>>>(adj);
    scan_kernel<<<1, 1024>>>();
    scatter_kernel<<<NE / 256, 256>>>(adj);
    transpose_kernel<<<dim3(NN / 32, DF / 32), dim3(32, 8)>>>(x);
    agg_kernel<<<NN, 128>>>();

    cudaFuncSetAttribute(gemm_kernel, cudaFuncAttributeMaxDynamicSharedMemorySize, GEMM_SMEM);
    gemm_kernel<<<dim3(DF / BN, NN / BM), 256, GEMM_SMEM>>>(W, out);
}

// round 7
// speedup vs baseline: 1.7379x; 1.0451x over previous
#include <cuda_runtime.h>
#include <cuda_fp16.h>
#include <cstdint>
#include <cstddef>

#define NN 8192      // nodes == in_feats
#define DF 512       // feature dim
#define NE 262144    // edges

// ---------------- device scratch (no allocations allowed) ----------------
__device__ int    g_deg[NN];
__device__ int    g_off[NN + 1];
__device__ int    g_cur[NN];
__device__ int    g_col[NE];
__device__ __half g_xh[(size_t)NN * DF];      // [node, feat] fp16, 8MB
__device__ __half g_hh[(size_t)DF * NN];      // [feat(n), node(k)] fp16 B operand, 8MB

// ---------------- helpers ----------------
__device__ __forceinline__ uint32_t smem_u32(const void* p) {
    uint32_t a;
    asm("{ .reg .u64 t; cvta.to.shared.u64 t, %1; cvt.u32.u64 %0, t; }"
        : "=r"(a) : "l"(p));
    return a;
}
__device__ __forceinline__ void cp_async16(uint32_t saddr, const void* gaddr) {
    asm volatile("cp.async.cg.shared.global [%0], [%1], 16;"
                 :: "r"(saddr), "l"(gaddr) : "memory");
}
#define CP_COMMIT() asm volatile("cp.async.commit_group;" ::: "memory")
#define CP_WAIT1()  asm volatile("cp.async.wait_group 1;"  ::: "memory")
#define CP_WAIT0()  asm volatile("cp.async.wait_group 0;"  ::: "memory")

#define LDSM4(r0, r1, r2, r3, addr) \
    asm volatile("ldmatrix.sync.aligned.m8n8.x4.shared.b16 {%0,%1,%2,%3}, [%4];" \
                 : "=r"(r0), "=r"(r1), "=r"(r2), "=r"(r3) : "r"(addr))

__device__ __forceinline__ void mma_f16(float* c,
                                        uint32_t a0, uint32_t a1, uint32_t a2, uint32_t a3,
                                        uint32_t b0, uint32_t b1) {
    asm volatile(
        "mma.sync.aligned.m16n8k16.row.col.f32.f16.f16.f32 "
        "{%0,%1,%2,%3}, {%4,%5,%6,%7}, {%8,%9}, {%0,%1,%2,%3};"
        : "+f"(c[0]), "+f"(c[1]), "+f"(c[2]), "+f"(c[3])
        : "r"(a0), "r"(a1), "r"(a2), "r"(a3), "r"(b0), "r"(b1));
}

// ---------------- fused prep head: transpose || zero out || zero deg ----------------
// blocks [0,4096): transpose x [DF,NN] f32 -> g_xh [NN,DF] fp16 (32x32 tiles)
// blocks [4096,8192): zero out (float4 each thread)
// block 8192: zero g_deg
__global__ void k0_kernel(const float* __restrict__ x, float* __restrict__ out) {
    int b = blockIdx.x;
    int tid = threadIdx.x;
    if (b < 4096) {
        __shared__ float tile[32][33];
        int n0 = (b & 255) * 32;
        int d0 = (b >> 8) * 32;
        int tx = tid & 31, ty = tid >> 5;   // ty 0..7
#pragma unroll
        for (int i = 0; i < 32; i += 8)
            tile[ty + i][tx] = x[(size_t)(d0 + ty + i) * NN + n0 + tx];
        __syncthreads();
#pragma unroll
        for (int i = 0; i < 32; i += 8)
            g_xh[(size_t)(n0 + ty + i) * DF + d0 + tx] = __float2half_rn(tile[tx][ty + i]);
    } else if (b < 8192) {
        size_t i = ((size_t)(b - 4096) * 256 + tid) * 4;
        *reinterpret_cast<float4*>(out + i) = make_float4(0.f, 0.f, 0.f, 0.f);
    } else {
#pragma unroll
        for (int j = 0; j < 32; ++j) g_deg[tid + 256 * j] = 0;
    }
}

__global__ void count_deg_kernel(const int* __restrict__ adj) {
    int e = blockIdx.x * 256 + threadIdx.x;
    atomicAdd(&g_deg[adj[e]], 1);
}

// exclusive scan of 8192 degrees: 1024 threads, shfl hierarchical
__global__ void scan_kernel() {
    __shared__ int wsum[32];
    int t = threadIdx.x, lane = t & 31, wid = t >> 5;
    int base = t * 8;
    int l[8];
    int s = 0;
#pragma unroll
    for (int j = 0; j < 8; ++j) { s += g_deg[base + j]; l[j] = s; }
    int tot = s;
#pragma unroll
    for (int o = 1; o < 32; o <<= 1) {
        int v = __shfl_up_sync(0xffffffffu, s, o);
        if (lane >= o) s += v;
    }
    if (lane == 31) wsum[wid] = s;
    __syncthreads();
    if (wid == 0) {
        int w = wsum[lane];
#pragma unroll
        for (int o = 1; o < 32; o <<= 1) {
            int v = __shfl_up_sync(0xffffffffu, w, o);
            if (lane >= o) w += v;
        }
        wsum[lane] = w;
    }
    __syncthreads();
    int warp_base = wid ? wsum[wid - 1] : 0;
    int excl = warp_base + s - tot;
#pragma unroll
    for (int j = 0; j < 8; ++j) {
        int e = excl + ((j == 0) ? 0 : l[j - 1]);
        g_off[base + j] = e;
        g_cur[base + j] = e;
    }
    if (t == 1023) g_off[NN] = warp_base + s;
}

__global__ void scatter_kernel(const int* __restrict__ adj) {
    int e = blockIdx.x * 256 + threadIdx.x;
    int r = adj[e];
    int c = adj[NE + e];
    int pos = atomicAdd(&g_cur[r], 1);
    g_col[pos] = c;
}

// one block per node: gather fp16 neighbor rows (4-edge unroll), f32 acc, write h fp16
__global__ void agg_kernel() {
    int r = blockIdx.x;
    int t = threadIdx.x;  // 0..127 -> 512 feats as 4 halves each
    int beg = g_off[r];
    int end = g_off[r + 1];
    const uint2* xh = reinterpret_cast<const uint2*>(g_xh);
    float ax = 0.f, ay = 0.f, az = 0.f, aw = 0.f;
    int j = beg;
    for (; j + 4 <= end; j += 4) {
        int c0 = g_col[j], c1 = g_col[j + 1], c2 = g_col[j + 2], c3 = g_col[j + 3];
        uint2 v0 = xh[(size_t)c0 * 128 + t];
        uint2 v1 = xh[(size_t)c1 * 128 + t];
        uint2 v2 = xh[(size_t)c2 * 128 + t];
        uint2 v3 = xh[(size_t)c3 * 128 + t];
#define ACCUM(v) do {                                              \
        __half2 h0 = *reinterpret_cast<__half2*>(&(v).x);          \
        __half2 h1 = *reinterpret_cast<__half2*>(&(v).y);          \
        float2 f0 = __half22float2(h0);                            \
        float2 f1 = __half22float2(h1);                            \
        ax += f0.x; ay += f0.y; az += f1.x; aw += f1.y; } while (0)
        ACCUM(v0); ACCUM(v1); ACCUM(v2); ACCUM(v3);
    }
    for (; j < end; ++j) {
        int c = g_col[j];
        uint2 v = xh[(size_t)c * 128 + t];
        ACCUM(v);
    }
#undef ACCUM
    float inv = 1.0f / fmaxf((float)(end - beg), 1.0f);
    int d = t * 4;
    g_hh[(size_t)(d + 0) * NN + r] = __float2half_rn(ax * inv);
    g_hh[(size_t)(d + 1) * NN + r] = __float2half_rn(ay * inv);
    g_hh[(size_t)(d + 2) * NN + r] = __float2half_rn(az * inv);
    g_hh[(size_t)(d + 3) * NN + r] = __float2half_rn(aw * inv);
}

// ---------------- balanced persistent fp16 GEMM ----------------
// 256 tiles (128m x 128n) x 128 k-chunks = 32768 chunk-works, statically
// range-split over G (=SM count) CTAs. Tiles n-major (tile = n*64 + m) so
// same-m CTAs run concurrently G/4 apart -> W dedups in L2.
// Full tiles: plain STG of raw sums. Split tiles (<=2 writers): atomicAdd
// into pre-zeroed out (2-float add is order-commutative -> deterministic).
// Final relu kernel applies max(0, .).

#define BM 128
#define BN 128
#define BK 64
#define NKC 128               // k-chunks per tile
#define TOTC 32768            // 256 tiles * 128 chunks
#define TILE_BYTES 16384
#define A_REGION 0
#define B_REGION 32768
#define GEMM_SMEM 81920

__device__ __forceinline__ uint32_t swz(int row, int colb) {
    return (uint32_t)(row * 128 + (colb ^ ((row & 7) << 4)));
}

__global__ __launch_bounds__(256, 1)
void gemm_kernel(const float* __restrict__ W, float* __restrict__ out, int G) {
    extern __shared__ char smem[];
    uint32_t sb = smem_u32(smem);
    int tid  = threadIdx.x;
    int wid  = tid >> 5;
    int lane = tid & 31;

    int warp_m = (wid & 1) * 64;
    int warp_n = (wid >> 1) * 32;
    int lq = lane & 3, lh = lane >> 2;

    // ldmatrix address components (within a stage tile)
    int a_r_lane = (lane & 7) + 8 * ((lane >> 3) & 1);
    uint32_t a_kx = (uint32_t)(16 * (lane >> 4));
    uint32_t a_row128[4], a_xr[4];
#pragma unroll
    for (int mt = 0; mt < 4; ++mt) {
        int r = warp_m + mt * 16 + a_r_lane;
        a_row128[mt] = (uint32_t)(r * 128);
        a_xr[mt] = (uint32_t)((r & 7) << 4);
    }
    uint32_t b_kx = (uint32_t)(16 * ((lane >> 3) & 1));
    uint32_t b_row128[2], b_xr[2];
#pragma unroll
    for (int p = 0; p < 2; ++p) {
        int n = warp_n + (2 * p + (lane >> 4)) * 8 + (lane & 7);
        b_row128[p] = (uint32_t)(n * 128);
        b_xr[p] = (uint32_t)((n & 7) << 4);
    }

    int a_r0 = tid >> 4;          // +16*i
    int a_c4 = tid & 15;          // float4 col in row
    int b_gc = tid & 7;
    int b_gr = tid >> 3;          // +32*i

    const __half* B = g_hh;
    float4 areg[8];

    int cta = blockIdx.x;
    int s = (int)(((long long)TOTC * cta) / G);
    int e = (int)(((long long)TOTC * (cta + 1)) / G);

    while (s < e) {
        int tile = s >> 7;
        int k0 = s - (tile << 7);
        int kend = e - (tile << 7);
        if (kend > NKC) kend = NKC;
        int nk = kend - k0;
        int m0 = (tile & 63) * BM;       // n-major tile order
        int n0 = (tile >> 6) * BN;
        bool full = (k0 == 0 && kend == NKC);

        float acc[4][4][4];
#pragma unroll
        for (int mt = 0; mt < 4; ++mt)
#pragma unroll
            for (int nt = 0; nt < 4; ++nt)
#pragma unroll
                for (int i = 0; i < 4; ++i) acc[mt][nt][i] = 0.f;

        // A chunk loaders (kt = global chunk index within this tile's k)
        auto ldA = [&](int kt) {
#pragma unroll
            for (int i = 0; i < 8; ++i) {
                int row = a_r0 + i * 16;
                areg[i] = *reinterpret_cast<const float4*>(
                    W + (size_t)(m0 + row) * NN + kt * BK + a_c4 * 4);
            }
        };
        auto stsA = [&](int stage) {
            char* ab = smem + A_REGION + stage * TILE_BYTES;
            int colb = a_c4 * 8;
#pragma unroll
            for (int i = 0; i < 8; ++i) {
                int row = a_r0 + i * 16;
                uint32_t off = (uint32_t)(row * 128 + (colb ^ ((row & 7) << 4)));
                __half2 h0 = __floats2half2_rn(areg[i].x, areg[i].y);
                __half2 h1 = __floats2half2_rn(areg[i].z, areg[i].w);
                uint2 v;
                v.x = *reinterpret_cast<uint32_t*>(&h0);
                v.y = *reinterpret_cast<uint32_t*>(&h1);
                *reinterpret_cast<uint2*>(ab + off) = v;
            }
        };
        auto cpB = [&](int kt, int stage) {
            uint32_t bbuf = sb + B_REGION + stage * TILE_BYTES;
#pragma unroll
            for (int i = 0; i < 4; ++i) {
                int row = b_gr + i * 32;
                uint32_t so = swz(row, b_gc * 16);
                cp_async16(bbuf + so, B + (size_t)(n0 + row) * NN + kt * BK + b_gc * 8);
            }
            CP_COMMIT();
        };

        // prologue
        ldA(k0);
        cpB(k0, 0);
        if (nk > 1) cpB(k0 + 1, 1);
        stsA(0);
        if (nk > 1) ldA(k0 + 1);

        for (int i = 0; i < nk; ++i) {
            if (i == nk - 1) { CP_WAIT0(); } else { CP_WAIT1(); }
            __syncthreads();

            if (i + 1 < nk) stsA((i + 1) & 1);
            if (i + 2 < nk) {
                ldA(k0 + i + 2);
                cpB(k0 + i + 2, (i + 2) % 3);
            }

            uint32_t abuf = sb + A_REGION + (i & 1) * TILE_BYTES;
            uint32_t bbuf = sb + B_REGION + (i % 3) * TILE_BYTES;

#pragma unroll
            for (int c = 0; c < 4; ++c) {
                uint32_t cb = (uint32_t)(c * 32);
                uint32_t af[4][4];
#pragma unroll
                for (int mt = 0; mt < 4; ++mt) {
                    uint32_t ptr = abuf + a_row128[mt] + ((cb + a_kx) ^ a_xr[mt]);
                    LDSM4(af[mt][0], af[mt][1], af[mt][2], af[mt][3], ptr);
                }
                uint32_t bf[4][2];
#pragma unroll
                for (int p = 0; p < 2; ++p) {
                    uint32_t ptr = bbuf + b_row128[p] + ((cb + b_kx) ^ b_xr[p]);
                    uint32_t r0, r1, r2, r3;
                    LDSM4(r0, r1, r2, r3, ptr);
                    bf[2 * p][0] = r0;     bf[2 * p][1] = r1;
                    bf[2 * p + 1][0] = r2; bf[2 * p + 1][1] = r3;
                }
#pragma unroll
                for (int mt = 0; mt < 4; ++mt)
#pragma unroll
                    for (int nt = 0; nt < 4; ++nt)
                        mma_f16(acc[mt][nt],
                                af[mt][0], af[mt][1], af[mt][2], af[mt][3],
                                bf[nt][0], bf[nt][1]);
            }
        }

        // epilogue: raw sums; relu applied by final pass
#pragma unroll
        for (int mt = 0; mt < 4; ++mt) {
            int m_lo = m0 + warp_m + mt * 16 + lh;
            int m_hi = m_lo + 8;
#pragma unroll
            for (int nt = 0; nt < 4; ++nt) {
                int nb = n0 + warp_n + nt * 8 + 2 * lq;
                float* o0 = out + (size_t)nb * NN;
                float* o1 = o0 + NN;
                if (full) {
                    o0[m_lo] = acc[mt][nt][0];
                    o1[m_lo] = acc[mt][nt][1];
                    o0[m_hi] = acc[mt][nt][2];
                    o1[m_hi] = acc[mt][nt][3];
                } else {
                    atomicAdd(o0 + m_lo, acc[mt][nt][0]);
                    atomicAdd(o1 + m_lo, acc[mt][nt][1]);
                    atomicAdd(o0 + m_hi, acc[mt][nt][2]);
                    atomicAdd(o1 + m_hi, acc[mt][nt][3]);
                }
            }
        }
        __syncthreads();   // smem reuse fence before next segment's stores

        s = (tile << 7) + kend;
    }
}

__global__ void relu_kernel(float* __restrict__ out) {
    size_t i = ((size_t)blockIdx.x * 256 + threadIdx.x) * 4;
    float4 v = *reinterpret_cast<float4*>(out + i);
    v.x = fmaxf(v.x, 0.f); v.y = fmaxf(v.y, 0.f);
    v.z = fmaxf(v.z, 0.f); v.w = fmaxf(v.w, 0.f);
    *reinterpret_cast<float4*>(out + i) = v;
}

// ---------------- launcher ----------------
extern "C" void kernel_launch(void* const* d_in, const int* in_sizes, int n_in,
                              void* d_out, int out_size) {
    (void)in_sizes; (void)n_in; (void)out_size;
    const float* x   = (const float*)d_in[0];   // [512, 8192] f32
    const int*   adj = (const int*)d_in[1];     // [2, 262144] i32
    const float* W   = (const float*)d_in[2];   // [8192, 8192] f32
    float* out = (float*)d_out;                 // [512, 8192] f32

    int dev = 0, G = 148;
    cudaGetDevice(&dev);
    cudaDeviceGetAttribute(&G, cudaDevAttrMultiProcessorCount, dev);

    k0_kernel<<<8193, 256>>>(x, out);
    count_deg_kernel<<<NE / 256, 256>>>(adj);
    scan_kernel<<<1, 1024>>>();
    scatter_kernel<<<NE / 256, 256>>>(adj);
    agg_kernel<<<NN, 128>>>();

    cudaFuncSetAttribute(gemm_kernel, cudaFuncAttributeMaxDynamicSharedMemorySize, GEMM_SMEM);
    gemm_kernel<<<G, 256, GEMM_SMEM>>>(W, out, G);
    relu_kernel<<<(int)(((size_t)DF * NN) / 1024), 256>>>(out);
}

// round 8
// speedup vs baseline: 1.7471x; 1.0053x over previous
#include <cuda_runtime.h>
#include <cuda_fp16.h>
#include <cstdint>
#include <cstddef>

#define NN 8192      // nodes == in_feats
#define DF 512       // feature dim
#define NE 262144    // edges

// ---------------- device scratch (no allocations allowed) ----------------
__device__ int    g_deg[NN];
__device__ int    g_off[NN + 1];
__device__ int    g_cur[NN];
__device__ int    g_col[NE];
__device__ int    g_cnt[256];                 // split-tile completion counters
__device__ __half g_xh[(size_t)NN * DF];      // [node, feat] fp16, 8MB
__device__ __half g_hT[(size_t)NN * DF];      // [node(k), feat(n)] fp16 B operand, 8MB

// ---------------- helpers ----------------
__device__ __forceinline__ uint32_t smem_u32(const void* p) {
    uint32_t a;
    asm("{ .reg .u64 t; cvta.to.shared.u64 t, %1; cvt.u32.u64 %0, t; }"
        : "=r"(a) : "l"(p));
    return a;
}
__device__ __forceinline__ void cp_async16(uint32_t saddr, const void* gaddr) {
    asm volatile("cp.async.cg.shared.global [%0], [%1], 16;"
                 :: "r"(saddr), "l"(gaddr) : "memory");
}
#define CP_COMMIT() asm volatile("cp.async.commit_group;" ::: "memory")
#define CP_WAIT1()  asm volatile("cp.async.wait_group 1;"  ::: "memory")
#define CP_WAIT0()  asm volatile("cp.async.wait_group 0;"  ::: "memory")

#define LDSM4(r0, r1, r2, r3, addr) \
    asm volatile("ldmatrix.sync.aligned.m8n8.x4.shared.b16 {%0,%1,%2,%3}, [%4];" \
                 : "=r"(r0), "=r"(r1), "=r"(r2), "=r"(r3) : "r"(addr))
#define LDSM4T(r0, r1, r2, r3, addr) \
    asm volatile("ldmatrix.sync.aligned.m8n8.x4.trans.shared.b16 {%0,%1,%2,%3}, [%4];" \
                 : "=r"(r0), "=r"(r1), "=r"(r2), "=r"(r3) : "r"(addr))

__device__ __forceinline__ void mma_f16(float* c,
                                        uint32_t a0, uint32_t a1, uint32_t a2, uint32_t a3,
                                        uint32_t b0, uint32_t b1) {
    asm volatile(
        "mma.sync.aligned.m16n8k16.row.col.f32.f16.f16.f32 "
        "{%0,%1,%2,%3}, {%4,%5,%6,%7}, {%8,%9}, {%0,%1,%2,%3};"
        : "+f"(c[0]), "+f"(c[1]), "+f"(c[2]), "+f"(c[3])
        : "r"(a0), "r"(a1), "r"(a2), "r"(a3), "r"(b0), "r"(b1));
}

// ---------------- fused prep head ----------------
// blocks [0,4096): transpose x [DF,NN] f32 -> g_xh [NN,DF] fp16
// blocks [4096,8192): zero out
// block 8192: zero g_deg + g_cnt
__global__ void k0_kernel(const float* __restrict__ x, float* __restrict__ out) {
    int b = blockIdx.x;
    int tid = threadIdx.x;
    if (b < 4096) {
        __shared__ float tile[32][33];
        int n0 = (b & 255) * 32;
        int d0 = (b >> 8) * 32;
        int tx = tid & 31, ty = tid >> 5;
#pragma unroll
        for (int i = 0; i < 32; i += 8)
            tile[ty + i][tx] = x[(size_t)(d0 + ty + i) * NN + n0 + tx];
        __syncthreads();
#pragma unroll
        for (int i = 0; i < 32; i += 8)
            g_xh[(size_t)(n0 + ty + i) * DF + d0 + tx] = __float2half_rn(tile[tx][ty + i]);
    } else if (b < 8192) {
        size_t i = ((size_t)(b - 4096) * 256 + tid) * 4;
        *reinterpret_cast<float4*>(out + i) = make_float4(0.f, 0.f, 0.f, 0.f);
    } else {
#pragma unroll
        for (int j = 0; j < 32; ++j) g_deg[tid + 256 * j] = 0;
        if (tid < 256) g_cnt[tid] = 0;
    }
}

__global__ void count_deg_kernel(const int* __restrict__ adj) {
    int e = blockIdx.x * 256 + threadIdx.x;
    atomicAdd(&g_deg[adj[e]], 1);
}

// exclusive scan of 8192 degrees: 1024 threads, shfl hierarchical
__global__ void scan_kernel() {
    __shared__ int wsum[32];
    int t = threadIdx.x, lane = t & 31, wid = t >> 5;
    int base = t * 8;
    int l[8];
    int s = 0;
#pragma unroll
    for (int j = 0; j < 8; ++j) { s += g_deg[base + j]; l[j] = s; }
    int tot = s;
#pragma unroll
    for (int o = 1; o < 32; o <<= 1) {
        int v = __shfl_up_sync(0xffffffffu, s, o);
        if (lane >= o) s += v;
    }
    if (lane == 31) wsum[wid] = s;
    __syncthreads();
    if (wid == 0) {
        int w = wsum[lane];
#pragma unroll
        for (int o = 1; o < 32; o <<= 1) {
            int v = __shfl_up_sync(0xffffffffu, w, o);
            if (lane >= o) w += v;
        }
        wsum[lane] = w;
    }
    __syncthreads();
    int warp_base = wid ? wsum[wid - 1] : 0;
    int excl = warp_base + s - tot;
#pragma unroll
    for (int j = 0; j < 8; ++j) {
        int e = excl + ((j == 0) ? 0 : l[j - 1]);
        g_off[base + j] = e;
        g_cur[base + j] = e;
    }
    if (t == 1023) g_off[NN] = warp_base + s;
}

__global__ void scatter_kernel(const int* __restrict__ adj) {
    int e = blockIdx.x * 256 + threadIdx.x;
    int r = adj[e];
    int c = adj[NE + e];
    int pos = atomicAdd(&g_cur[r], 1);
    g_col[pos] = c;
}

// one block per node: gather fp16 neighbor rows (4-edge unroll), f32 acc,
// write h^T CONTIGUOUSLY: g_hT[r*DF + d]
__global__ void agg_kernel() {
    int r = blockIdx.x;
    int t = threadIdx.x;  // 0..127 -> 512 feats as 4 halves each
    int beg = g_off[r];
    int end = g_off[r + 1];
    const uint2* xh = reinterpret_cast<const uint2*>(g_xh);
    float ax = 0.f, ay = 0.f, az = 0.f, aw = 0.f;
    int j = beg;
    for (; j + 4 <= end; j += 4) {
        int c0 = g_col[j], c1 = g_col[j + 1], c2 = g_col[j + 2], c3 = g_col[j + 3];
        uint2 v0 = xh[(size_t)c0 * 128 + t];
        uint2 v1 = xh[(size_t)c1 * 128 + t];
        uint2 v2 = xh[(size_t)c2 * 128 + t];
        uint2 v3 = xh[(size_t)c3 * 128 + t];
#define ACCUM(v) do {                                              \
        __half2 h0 = *reinterpret_cast<__half2*>(&(v).x);          \
        __half2 h1 = *reinterpret_cast<__half2*>(&(v).y);          \
        float2 f0 = __half22float2(h0);                            \
        float2 f1 = __half22float2(h1);                            \
        ax += f0.x; ay += f0.y; az += f1.x; aw += f1.y; } while (0)
        ACCUM(v0); ACCUM(v1); ACCUM(v2); ACCUM(v3);
    }
    for (; j < end; ++j) {
        int c = g_col[j];
        uint2 v = xh[(size_t)c * 128 + t];
        ACCUM(v);
    }
#undef ACCUM
    float inv = 1.0f / fmaxf((float)(end - beg), 1.0f);
    __half2 o0 = __floats2half2_rn(ax * inv, ay * inv);
    __half2 o1 = __floats2half2_rn(az * inv, aw * inv);
    uint2 v;
    v.x = *reinterpret_cast<uint32_t*>(&o0);
    v.y = *reinterpret_cast<uint32_t*>(&o1);
    *reinterpret_cast<uint2*>(g_hT + (size_t)r * DF + t * 4) = v;
}

// ---------------- balanced persistent fp16 GEMM, fused relu ----------------
// 256 tiles (128m x 128n) x 128 k-chunks = 32768 chunk-works split over G CTAs.
// A = W f32 (LDG->cvt->STS fp16, 2-stage). B = g_hT MN-major (cp.async, 3-stage,
// ldmatrix.trans). Full tiles: relu'd STG. Split tiles (<=2 writers,
// commutative -> deterministic): atomicAdd raw; last arriver (counter) relus tile.

#define BM 128
#define BN 128
#define BK 64
#define NKC 128
#define TOTC 32768
#define TILE_BYTES 16384
#define A_REGION 0
#define B_REGION 32768
#define GEMM_SMEM 81920

__device__ __forceinline__ int cta_of(int c, int G) {
    return (int)(((long long)(c + 1) * G - 1) / TOTC);
}

__global__ __launch_bounds__(256, 1)
void gemm_kernel(const float* __restrict__ W, float* __restrict__ out, int G) {
    extern __shared__ char smem[];
    __shared__ int s_old;
    uint32_t sb = smem_u32(smem);
    int tid  = threadIdx.x;
    int wid  = tid >> 5;
    int lane = tid & 31;

    int warp_m = (wid & 1) * 64;
    int warp_n = (wid >> 1) * 32;
    int lq = lane & 3, lh = lane >> 2;

    // A ldmatrix address components (128B rows, XOR swizzle)
    int a_r_lane = (lane & 7) + 8 * ((lane >> 3) & 1);
    uint32_t a_kx = (uint32_t)(16 * (lane >> 4));
    uint32_t a_row128[4], a_xr[4];
#pragma unroll
    for (int mt = 0; mt < 4; ++mt) {
        int r = warp_m + mt * 16 + a_r_lane;
        a_row128[mt] = (uint32_t)(r * 128);
        a_xr[mt] = (uint32_t)((r & 7) << 4);
    }
    // B ldmatrix.trans address components: tile is [64 k-rows x 256B(128 n fp16)]
    // lane group g=lane>>3: kr_local = (g&1)*8 + (lane&7); nc = warp_n + (2p + (g>>1))*8
    {
    }
    int g_grp = lane >> 3;
    int kr_local = (g_grp & 1) * 8 + (lane & 7);
    uint32_t b_off[2];
#pragma unroll
    for (int p = 0; p < 2; ++p) {
        int nc = warp_n + (2 * p + (g_grp >> 1)) * 8;
        b_off[p] = (uint32_t)(kr_local * 256 + ((nc * 2) ^ ((lane & 7) << 4)));
    }

    int a_r0 = tid >> 4;          // +16*i
    int a_c4 = tid & 15;          // float4 col in row
    int b_k  = tid >> 4;          // k-row 0..15, +16*i
    int b_nc = tid & 15;          // 16B n-chunk within 256B row

    const __half* B = g_hT;
    float4 areg[8];

    int cta = blockIdx.x;
    int s = (int)(((long long)TOTC * cta) / G);
    int e = (int)(((long long)TOTC * (cta + 1)) / G);

    while (s < e) {
        int tile = s >> 7;
        int k0 = s - (tile << 7);
        int kend = e - (tile << 7);
        if (kend > NKC) kend = NKC;
        int nk = kend - k0;
        int m0 = (tile & 63) * BM;       // n-major tile order
        int n0 = (tile >> 6) * BN;
        bool full = (k0 == 0 && kend == NKC);

        float acc[4][4][4];
#pragma unroll
        for (int mt = 0; mt < 4; ++mt)
#pragma unroll
            for (int nt = 0; nt < 4; ++nt)
#pragma unroll
                for (int i = 0; i < 4; ++i) acc[mt][nt][i] = 0.f;

        auto ldA = [&](int kt) {
#pragma unroll
            for (int i = 0; i < 8; ++i) {
                int row = a_r0 + i * 16;
                areg[i] = *reinterpret_cast<const float4*>(
                    W + (size_t)(m0 + row) * NN + kt * BK + a_c4 * 4);
            }
        };
        auto stsA = [&](int stage) {
            char* ab = smem + A_REGION + stage * TILE_BYTES;
            int colb = a_c4 * 8;
#pragma unroll
            for (int i = 0; i < 8; ++i) {
                int row = a_r0 + i * 16;
                uint32_t off = (uint32_t)(row * 128 + (colb ^ ((row & 7) << 4)));
                __half2 h0 = __floats2half2_rn(areg[i].x, areg[i].y);
                __half2 h1 = __floats2half2_rn(areg[i].z, areg[i].w);
                uint2 v;
                v.x = *reinterpret_cast<uint32_t*>(&h0);
                v.y = *reinterpret_cast<uint32_t*>(&h1);
                *reinterpret_cast<uint2*>(ab + off) = v;
            }
        };
        // B tile: 64 k-rows x 128 n fp16 (256B/row), rows k = kt*64..+63, cols n0..n0+127
        auto cpB = [&](int kt, int stage) {
            uint32_t bbuf = sb + B_REGION + stage * TILE_BYTES;
#pragma unroll
            for (int i = 0; i < 4; ++i) {
                int k = b_k + i * 16;
                uint32_t so = (uint32_t)(k * 256 + ((b_nc * 16) ^ ((k & 7) << 4)));
                cp_async16(bbuf + so, B + (size_t)(kt * BK + k) * DF + n0 + b_nc * 8);
            }
            CP_COMMIT();
        };

        ldA(k0);
        cpB(k0, 0);
        if (nk > 1) cpB(k0 + 1, 1);
        stsA(0);
        if (nk > 1) ldA(k0 + 1);

        for (int i = 0; i < nk; ++i) {
            if (i == nk - 1) { CP_WAIT0(); } else { CP_WAIT1(); }
            __syncthreads();

            if (i + 1 < nk) stsA((i + 1) & 1);
            if (i + 2 < nk) {
                ldA(k0 + i + 2);
                cpB(k0 + i + 2, (i + 2) % 3);
            }

            uint32_t abuf = sb + A_REGION + (i & 1) * TILE_BYTES;
            uint32_t bbuf = sb + B_REGION + (i % 3) * TILE_BYTES;

#pragma unroll
            for (int c = 0; c < 4; ++c) {
                uint32_t cb = (uint32_t)(c * 32);
                uint32_t af[4][4];
#pragma unroll
                for (int mt = 0; mt < 4; ++mt) {
                    uint32_t ptr = abuf + a_row128[mt] + ((cb + a_kx) ^ a_xr[mt]);
                    LDSM4(af[mt][0], af[mt][1], af[mt][2], af[mt][3], ptr);
                }
                uint32_t bf[4][2];
#pragma unroll
                for (int p = 0; p < 2; ++p) {
                    uint32_t ptr = bbuf + (uint32_t)(c * 4096) + b_off[p];
                    uint32_t r0, r1, r2, r3;
                    LDSM4T(r0, r1, r2, r3, ptr);
                    bf[2 * p][0] = r0;     bf[2 * p][1] = r1;
                    bf[2 * p + 1][0] = r2; bf[2 * p + 1][1] = r3;
                }
#pragma unroll
                for (int mt = 0; mt < 4; ++mt)
#pragma unroll
                    for (int nt = 0; nt < 4; ++nt)
                        mma_f16(acc[mt][nt],
                                af[mt][0], af[mt][1], af[mt][2], af[mt][3],
                                bf[nt][0], bf[nt][1]);
            }
        }

        // ---- epilogue ----
#pragma unroll
        for (int mt = 0; mt < 4; ++mt) {
            int m_lo = m0 + warp_m + mt * 16 + lh;
            int m_hi = m_lo + 8;
#pragma unroll
            for (int nt = 0; nt < 4; ++nt) {
                int nb = n0 + warp_n + nt * 8 + 2 * lq;
                float* o0 = out + (size_t)nb * NN;
                float* o1 = o0 + NN;
                if (full) {
                    o0[m_lo] = fmaxf(acc[mt][nt][0], 0.f);
                    o1[m_lo] = fmaxf(acc[mt][nt][1], 0.f);
                    o0[m_hi] = fmaxf(acc[mt][nt][2], 0.f);
                    o1[m_hi] = fmaxf(acc[mt][nt][3], 0.f);
                } else {
                    atomicAdd(o0 + m_lo, acc[mt][nt][0]);
                    atomicAdd(o1 + m_lo, acc[mt][nt][1]);
                    atomicAdd(o0 + m_hi, acc[mt][nt][2]);
                    atomicAdd(o1 + m_hi, acc[mt][nt][3]);
                }
            }
        }

        if (!full) {
            // last-arriver applies relu to the whole tile
            int writers = cta_of(tile * NKC + NKC - 1, G) - cta_of(tile * NKC, G) + 1;
            __threadfence();
            __syncthreads();
            if (tid == 0) s_old = atomicAdd(&g_cnt[tile], 1);
            __syncthreads();
            if (s_old == writers - 1) {
                __threadfence();
#pragma unroll
                for (int i = 0; i < 16; ++i) {
                    int idx = tid + i * 256;        // 4096 float4 = 128x128
                    int row = idx >> 5, c4 = idx & 31;
                    float4* pp = reinterpret_cast<float4*>(
                        out + (size_t)(n0 + row) * NN + m0) + c4;
                    float4 v = *pp;
                    v.x = fmaxf(v.x, 0.f); v.y = fmaxf(v.y, 0.f);
                    v.z = fmaxf(v.z, 0.f); v.w = fmaxf(v.w, 0.f);
                    *pp = v;
                }
            }
        }
        __syncthreads();   // smem reuse fence before next segment

        s = (tile << 7) + kend;
    }
}

// ---------------- launcher ----------------
extern "C" void kernel_launch(void* const* d_in, const int* in_sizes, int n_in,
                              void* d_out, int out_size) {
    (void)in_sizes; (void)n_in; (void)out_size;
    const float* x   = (const float*)d_in[0];   // [512, 8192] f32
    const int*   adj = (const int*)d_in[1];     // [2, 262144] i32
    const float* W   = (const float*)d_in[2];   // [8192, 8192] f32
    float* out = (float*)d_out;                 // [512, 8192] f32

    int dev = 0, G = 148;
    cudaGetDevice(&dev);
    cudaDeviceGetAttribute(&G, cudaDevAttrMultiProcessorCount, dev);

    k0_kernel<<<8193, 256>>>(x, out);
    count_deg_kernel<<<NE / 256, 256>>>(adj);
    scan_kernel<<<1, 1024>>>();
    scatter_kernel<<<NE / 256, 256>>>(adj);
    agg_kernel<<<NN, 128>>>();

    cudaFuncSetAttribute(gemm_kernel, cudaFuncAttributeMaxDynamicSharedMemorySize, GEMM_SMEM);
    gemm_kernel<<<G, 256, GEMM_SMEM>>>(W, out, G);
}

// round 9
// speedup vs baseline: 1.7533x; 1.0036x over previous
#include <cuda_runtime.h>
#include <cuda_fp16.h>
#include <cstdint>
#include <cstddef>

#define NN 8192      // nodes == in_feats
#define DF 512       // feature dim
#define NE 262144    // edges

// ---------------- device scratch (no allocations allowed) ----------------
// g_deg / g_cnt are zero at module load; every run re-zeroes them after use,
// so each graph replay deterministically sees zeroed state.
__device__ int    g_deg[NN];
__device__ int    g_off[NN + 1];
__device__ int    g_cur[NN];
__device__ int    g_col[NE];
__device__ int    g_cnt[256];                 // split-tile completion counters
__device__ __half g_xh[(size_t)NN * DF];      // [node, feat] fp16, 8MB
__device__ __half g_hT[(size_t)NN * DF];      // [node(k), feat(n)] fp16 B operand, 8MB

// ---------------- helpers ----------------
__device__ __forceinline__ uint32_t smem_u32(const void* p) {
    uint32_t a;
    asm("{ .reg .u64 t; cvta.to.shared.u64 t, %1; cvt.u32.u64 %0, t; }"
        : "=r"(a) : "l"(p));
    return a;
}
__device__ __forceinline__ void cp_async16(uint32_t saddr, const void* gaddr) {
    asm volatile("cp.async.cg.shared.global [%0], [%1], 16;"
                 :: "r"(saddr), "l"(gaddr) : "memory");
}
#define CP_COMMIT() asm volatile("cp.async.commit_group;" ::: "memory")
#define CP_WAIT1()  asm volatile("cp.async.wait_group 1;"  ::: "memory")
#define CP_WAIT0()  asm volatile("cp.async.wait_group 0;"  ::: "memory")

#define LDSM4(r0, r1, r2, r3, addr) \
    asm volatile("ldmatrix.sync.aligned.m8n8.x4.shared.b16 {%0,%1,%2,%3}, [%4];" \
                 : "=r"(r0), "=r"(r1), "=r"(r2), "=r"(r3) : "r"(addr))
#define LDSM4T(r0, r1, r2, r3, addr) \
    asm volatile("ldmatrix.sync.aligned.m8n8.x4.trans.shared.b16 {%0,%1,%2,%3}, [%4];" \
                 : "=r"(r0), "=r"(r1), "=r"(r2), "=r"(r3) : "r"(addr))

__device__ __forceinline__ void mma_f16(float* c,
                                        uint32_t a0, uint32_t a1, uint32_t a2, uint32_t a3,
                                        uint32_t b0, uint32_t b1) {
    asm volatile(
        "mma.sync.aligned.m16n8k16.row.col.f32.f16.f16.f32 "
        "{%0,%1,%2,%3}, {%4,%5,%6,%7}, {%8,%9}, {%0,%1,%2,%3};"
        : "+f"(c[0]), "+f"(c[1]), "+f"(c[2]), "+f"(c[3])
        : "r"(a0), "r"(a1), "r"(a2), "r"(a3), "r"(b0), "r"(b1));
}

// ---------------- fused prep head ----------------
// blocks [0,4096): transpose x [DF,NN] f32 -> g_xh [NN,DF] fp16
// blocks [4096,8192): zero out
// blocks [8192,8448): degree count, 4 edges/thread (g_deg pre-zeroed invariant)
__global__ void k0_kernel(const float* __restrict__ x, float* __restrict__ out,
                          const int* __restrict__ adj) {
    int b = blockIdx.x;
    int tid = threadIdx.x;
    if (b < 4096) {
        __shared__ float tile[32][33];
        int n0 = (b & 255) * 32;
        int d0 = (b >> 8) * 32;
        int tx = tid & 31, ty = tid >> 5;
#pragma unroll
        for (int i = 0; i < 32; i += 8)
            tile[ty + i][tx] = x[(size_t)(d0 + ty + i) * NN + n0 + tx];
        __syncthreads();
#pragma unroll
        for (int i = 0; i < 32; i += 8)
            g_xh[(size_t)(n0 + ty + i) * DF + d0 + tx] = __float2half_rn(tile[tx][ty + i]);
    } else if (b < 8192) {
        size_t i = ((size_t)(b - 4096) * 256 + tid) * 4;
        *reinterpret_cast<float4*>(out + i) = make_float4(0.f, 0.f, 0.f, 0.f);
    } else {
        int e4 = (b - 8192) * 256 + tid;              // 0..65535, 4 edges each
        int4 r = reinterpret_cast<const int4*>(adj)[e4];
        atomicAdd(&g_deg[r.x], 1);
        atomicAdd(&g_deg[r.y], 1);
        atomicAdd(&g_deg[r.z], 1);
        atomicAdd(&g_deg[r.w], 1);
    }
}

// exclusive scan of 8192 degrees; re-zero g_deg after reading (replay invariant)
__global__ void scan_kernel() {
    __shared__ int wsum[32];
    int t = threadIdx.x, lane = t & 31, wid = t >> 5;
    int base = t * 8;
    int l[8];
    int s = 0;
#pragma unroll
    for (int j = 0; j < 8; ++j) { s += g_deg[base + j]; l[j] = s; }
#pragma unroll
    for (int j = 0; j < 8; ++j) g_deg[base + j] = 0;
    int tot = s;
#pragma unroll
    for (int o = 1; o < 32; o <<= 1) {
        int v = __shfl_up_sync(0xffffffffu, s, o);
        if (lane >= o) s += v;
    }
    if (lane == 31) wsum[wid] = s;
    __syncthreads();
    if (wid == 0) {
        int w = wsum[lane];
#pragma unroll
        for (int o = 1; o < 32; o <<= 1) {
            int v = __shfl_up_sync(0xffffffffu, w, o);
            if (lane >= o) w += v;
        }
        wsum[lane] = w;
    }
    __syncthreads();
    int warp_base = wid ? wsum[wid - 1] : 0;
    int excl = warp_base + s - tot;
#pragma unroll
    for (int j = 0; j < 8; ++j) {
        int e = excl + ((j == 0) ? 0 : l[j - 1]);
        g_off[base + j] = e;
        g_cur[base + j] = e;
    }
    if (t == 1023) g_off[NN] = warp_base + s;
}

// 4 edges/thread, int4 loads of both adj rows
__global__ void scatter_kernel(const int* __restrict__ adj) {
    int e4 = blockIdx.x * 256 + threadIdx.x;   // 0..65535
    int4 r = reinterpret_cast<const int4*>(adj)[e4];
    int4 c = reinterpret_cast<const int4*>(adj)[NE / 4 + e4];
    g_col[atomicAdd(&g_cur[r.x], 1)] = c.x;
    g_col[atomicAdd(&g_cur[r.y], 1)] = c.y;
    g_col[atomicAdd(&g_cur[r.z], 1)] = c.z;
    g_col[atomicAdd(&g_cur[r.w], 1)] = c.w;
}

// one block per node: gather fp16 neighbor rows (4-edge unroll), f32 acc,
// write h^T contiguously: g_hT[r*DF + d]
__global__ void agg_kernel() {
    int r = blockIdx.x;
    int t = threadIdx.x;  // 0..127 -> 512 feats as 4 halves each
    int beg = g_off[r];
    int end = g_off[r + 1];
    const uint2* xh = reinterpret_cast<const uint2*>(g_xh);
    float ax = 0.f, ay = 0.f, az = 0.f, aw = 0.f;
    int j = beg;
    for (; j + 4 <= end; j += 4) {
        int c0 = g_col[j], c1 = g_col[j + 1], c2 = g_col[j + 2], c3 = g_col[j + 3];
        uint2 v0 = xh[(size_t)c0 * 128 + t];
        uint2 v1 = xh[(size_t)c1 * 128 + t];
        uint2 v2 = xh[(size_t)c2 * 128 + t];
        uint2 v3 = xh[(size_t)c3 * 128 + t];
#define ACCUM(v) do {                                              \
        __half2 h0 = *reinterpret_cast<__half2*>(&(v).x);          \
        __half2 h1 = *reinterpret_cast<__half2*>(&(v).y);          \
        float2 f0 = __half22float2(h0);                            \
        float2 f1 = __half22float2(h1);                            \
        ax += f0.x; ay += f0.y; az += f1.x; aw += f1.y; } while (0)
        ACCUM(v0); ACCUM(v1); ACCUM(v2); ACCUM(v3);
    }
    for (; j < end; ++j) {
        int c = g_col[j];
        uint2 v = xh[(size_t)c * 128 + t];
        ACCUM(v);
    }
#undef ACCUM
    float inv = 1.0f / fmaxf((float)(end - beg), 1.0f);
    __half2 o0 = __floats2half2_rn(ax * inv, ay * inv);
    __half2 o1 = __floats2half2_rn(az * inv, aw * inv);
    uint2 v;
    v.x = *reinterpret_cast<uint32_t*>(&o0);
    v.y = *reinterpret_cast<uint32_t*>(&o1);
    *reinterpret_cast<uint2*>(g_hT + (size_t)r * DF + t * 4) = v;
}

// ---------------- balanced persistent fp16 GEMM, fused relu ----------------
#define BM 128
#define BN 128
#define BK 64
#define NKC 128
#define TOTC 32768
#define TILE_BYTES 16384
#define A_REGION 0
#define B_REGION 32768
#define GEMM_SMEM 81920

__device__ __forceinline__ int cta_of(int c, int G) {
    return (int)(((long long)(c + 1) * G - 1) / TOTC);
}

__global__ __launch_bounds__(256, 1)
void gemm_kernel(const float* __restrict__ W, float* __restrict__ out, int G) {
    extern __shared__ char smem[];
    __shared__ int s_old;
    uint32_t sb = smem_u32(smem);
    int tid  = threadIdx.x;
    int wid  = tid >> 5;
    int lane = tid & 31;

    int warp_m = (wid & 1) * 64;
    int warp_n = (wid >> 1) * 32;
    int lq = lane & 3, lh = lane >> 2;

    int a_r_lane = (lane & 7) + 8 * ((lane >> 3) & 1);
    uint32_t a_kx = (uint32_t)(16 * (lane >> 4));
    uint32_t a_row128[4], a_xr[4];
#pragma unroll
    for (int mt = 0; mt < 4; ++mt) {
        int r = warp_m + mt * 16 + a_r_lane;
        a_row128[mt] = (uint32_t)(r * 128);
        a_xr[mt] = (uint32_t)((r & 7) << 4);
    }
    int g_grp = lane >> 3;
    int kr_local = (g_grp & 1) * 8 + (lane & 7);
    uint32_t b_off[2];
#pragma unroll
    for (int p = 0; p < 2; ++p) {
        int nc = warp_n + (2 * p + (g_grp >> 1)) * 8;
        b_off[p] = (uint32_t)(kr_local * 256 + ((nc * 2) ^ ((lane & 7) << 4)));
    }

    int a_r0 = tid >> 4;
    int a_c4 = tid & 15;
    int b_k  = tid >> 4;
    int b_nc = tid & 15;

    const __half* B = g_hT;
    float4 areg[8];

    int cta = blockIdx.x;
    int s = (int)(((long long)TOTC * cta) / G);
    int e = (int)(((long long)TOTC * (cta + 1)) / G);

    while (s < e) {
        int tile = s >> 7;
        int k0 = s - (tile << 7);
        int kend = e - (tile << 7);
        if (kend > NKC) kend = NKC;
        int nk = kend - k0;
        int m0 = (tile & 63) * BM;
        int n0 = (tile >> 6) * BN;
        bool full = (k0 == 0 && kend == NKC);

        float acc[4][4][4];
#pragma unroll
        for (int mt = 0; mt < 4; ++mt)
#pragma unroll
            for (int nt = 0; nt < 4; ++nt)
#pragma unroll
                for (int i = 0; i < 4; ++i) acc[mt][nt][i] = 0.f;

        auto ldA = [&](int kt) {
#pragma unroll
            for (int i = 0; i < 8; ++i) {
                int row = a_r0 + i * 16;
                areg[i] = *reinterpret_cast<const float4*>(
                    W + (size_t)(m0 + row) * NN + kt * BK + a_c4 * 4);
            }
        };
        auto stsA = [&](int stage) {
            char* ab = smem + A_REGION + stage * TILE_BYTES;
            int colb = a_c4 * 8;
#pragma unroll
            for (int i = 0; i < 8; ++i) {
                int row = a_r0 + i * 16;
                uint32_t off = (uint32_t)(row * 128 + (colb ^ ((row & 7) << 4)));
                __half2 h0 = __floats2half2_rn(areg[i].x, areg[i].y);
                __half2 h1 = __floats2half2_rn(areg[i].z, areg[i].w);
                uint2 v;
                v.x = *reinterpret_cast<uint32_t*>(&h0);
                v.y = *reinterpret_cast<uint32_t*>(&h1);
                *reinterpret_cast<uint2*>(ab + off) = v;
            }
        };
        auto cpB = [&](int kt, int stage) {
            uint32_t bbuf = sb + B_REGION + stage * TILE_BYTES;
#pragma unroll
            for (int i = 0; i < 4; ++i) {
                int k = b_k + i * 16;
                uint32_t so = (uint32_t)(k * 256 + ((b_nc * 16) ^ ((k & 7) << 4)));
                cp_async16(bbuf + so, B + (size_t)(kt * BK + k) * DF + n0 + b_nc * 8);
            }
            CP_COMMIT();
        };

        ldA(k0);
        cpB(k0, 0);
        if (nk > 1) cpB(k0 + 1, 1);
        stsA(0);
        if (nk > 1) ldA(k0 + 1);

        for (int i = 0; i < nk; ++i) {
            if (i == nk - 1) { CP_WAIT0(); } else { CP_WAIT1(); }
            __syncthreads();

            if (i + 1 < nk) stsA((i + 1) & 1);
            if (i + 2 < nk) {
                ldA(k0 + i + 2);
                cpB(k0 + i + 2, (i + 2) % 3);
            }

            uint32_t abuf = sb + A_REGION + (i & 1) * TILE_BYTES;
            uint32_t bbuf = sb + B_REGION + (i % 3) * TILE_BYTES;

#pragma unroll
            for (int c = 0; c < 4; ++c) {
                uint32_t cb = (uint32_t)(c * 32);
                uint32_t af[4][4];
#pragma unroll
                for (int mt = 0; mt < 4; ++mt) {
                    uint32_t ptr = abuf + a_row128[mt] + ((cb + a_kx) ^ a_xr[mt]);
                    LDSM4(af[mt][0], af[mt][1], af[mt][2], af[mt][3], ptr);
                }
                uint32_t bf[4][2];
#pragma unroll
                for (int p = 0; p < 2; ++p) {
                    uint32_t ptr = bbuf + (uint32_t)(c * 4096) + b_off[p];
                    uint32_t r0, r1, r2, r3;
                    LDSM4T(r0, r1, r2, r3, ptr);
                    bf[2 * p][0] = r0;     bf[2 * p][1] = r1;
                    bf[2 * p + 1][0] = r2; bf[2 * p + 1][1] = r3;
                }
#pragma unroll
                for (int mt = 0; mt < 4; ++mt)
#pragma unroll
                    for (int nt = 0; nt < 4; ++nt)
                        mma_f16(acc[mt][nt],
                                af[mt][0], af[mt][1], af[mt][2], af[mt][3],
                                bf[nt][0], bf[nt][1]);
            }
        }

#pragma unroll
        for (int mt = 0; mt < 4; ++mt) {
            int m_lo = m0 + warp_m + mt * 16 + lh;
            int m_hi = m_lo + 8;
#pragma unroll
            for (int nt = 0; nt < 4; ++nt) {
                int nb = n0 + warp_n + nt * 8 + 2 * lq;
                float* o0 = out + (size_t)nb * NN;
                float* o1 = o0 + NN;
                if (full) {
                    o0[m_lo] = fmaxf(acc[mt][nt][0], 0.f);
                    o1[m_lo] = fmaxf(acc[mt][nt][1], 0.f);
                    o0[m_hi] = fmaxf(acc[mt][nt][2], 0.f);
                    o1[m_hi] = fmaxf(acc[mt][nt][3], 0.f);
                } else {
                    atomicAdd(o0 + m_lo, acc[mt][nt][0]);
                    atomicAdd(o1 + m_lo, acc[mt][nt][1]);
                    atomicAdd(o0 + m_hi, acc[mt][nt][2]);
                    atomicAdd(o1 + m_hi, acc[mt][nt][3]);
                }
            }
        }

        if (!full) {
            int writers = cta_of(tile * NKC + NKC - 1, G) - cta_of(tile * NKC, G) + 1;
            __threadfence();
            __syncthreads();
            if (tid == 0) s_old = atomicAdd(&g_cnt[tile], 1);
            __syncthreads();
            if (s_old == writers - 1) {
                __threadfence();
#pragma unroll
                for (int i = 0; i < 16; ++i) {
                    int idx = tid + i * 256;
                    int row = idx >> 5, c4 = idx & 31;
                    float4* pp = reinterpret_cast<float4*>(
                        out + (size_t)(n0 + row) * NN + m0) + c4;
                    float4 v = *pp;
                    v.x = fmaxf(v.x, 0.f); v.y = fmaxf(v.y, 0.f);
                    v.z = fmaxf(v.z, 0.f); v.w = fmaxf(v.w, 0.f);
                    *pp = v;
                }
                if (tid == 0) g_cnt[tile] = 0;   // replay invariant
            }
        }
        __syncthreads();

        s = (tile << 7) + kend;
    }
}

// ---------------- launcher ----------------
extern "C" void kernel_launch(void* const* d_in, const int* in_sizes, int n_in,
                              void* d_out, int out_size) {
    (void)in_sizes; (void)n_in; (void)out_size;
    const float* x   = (const float*)d_in[0];   // [512, 8192] f32
    const int*   adj = (const int*)d_in[1];     // [2, 262144] i32
    const float* W   = (const float*)d_in[2];   // [8192, 8192] f32
    float* out = (float*)d_out;                 // [512, 8192] f32

    int dev = 0, G = 148;
    cudaGetDevice(&dev);
    cudaDeviceGetAttribute(&G, cudaDevAttrMultiProcessorCount, dev);

    k0_kernel<<<8448, 256>>>(x, out, adj);
    scan_kernel<<<1, 1024>>>();
    scatter_kernel<<<NE / 1024, 256>>>(adj);
    agg_kernel<<<NN, 128>>>();

    cudaFuncSetAttribute(gemm_kernel, cudaFuncAttributeMaxDynamicSharedMemorySize, GEMM_SMEM);
    gemm_kernel<<<G, 256, GEMM_SMEM>>>(W, out, G);
}